// round 9
// baseline (speedup 1.0000x reference)
#include <cuda_runtime.h>
#include <cstdint>

// Conv2d: x[3,2048,2048] fp32 * k[16,3,3,3] fp32, pad=1, stride=1 -> out[16,2048,2048]
//
// R8: direct conv, fma.rn.f32x2, crossbar-byte-minimal loads + high occupancy.
//   - block = 512 threads: 32 tx (4 px) x 4 ty (rows) x 4 og (4 OC each).
//     Tile = 4 rows x 128 cols x 16 OC. grid (16, 512).
//   - input rows plain fp32 in smem; per tap-row ONE float4 + ONE float2
//     (24 B/thread, each value loaded once); shifted pairs built with packs.
//   - weights (w,w)-packed u64, warp-uniform ulonglong2 loads, sequenced wa->wb.
//   - __launch_bounds__(512,3): 42-reg cap, 3 CTAs x 16 warps = 48 warps/SM (75% occ).
//   - per thread: 216 FFMA2, 18 input LDS, 54 weight LDS, ~45 pack MOVs.

#define HW    2048
#define PLANE (2048 * 2048)

typedef unsigned long long u64;

__device__ __forceinline__ u64 pack2(float a, float b) {
    u64 r;
    asm("mov.b64 %0, {%1, %2};"
        : "=l"(r) : "r"(__float_as_uint(a)), "r"(__float_as_uint(b)));
    return r;
}

__device__ __forceinline__ void ffma2(u64& d, u64 a, u64 b) {
    asm("fma.rn.f32x2 %0, %1, %2, %0;" : "+l"(d) : "l"(a), "l"(b));
}

__device__ __forceinline__ float2 unpack2(u64 v) {
    unsigned lo, hi;
    asm("mov.b64 {%0, %1}, %2;" : "=r"(lo), "=r"(hi) : "l"(v));
    return make_float2(__uint_as_float(lo), __uint_as_float(hi));
}

__global__ __launch_bounds__(512, 3)
void conv3x3_f32x2_v6_kernel(const float* __restrict__ x,
                             const float* __restrict__ kern,
                             float* __restrict__ out) {
    // Input tile: 3 ch, 4+2 rows, 128+2 cols padded to 132 (16B-aligned rows).
    __shared__ __align__(16) float s_in[3][6][132];
    // Weights (w,w)-packed, layout [tap][oc16], tap = ic*9 + kh*3 + kw.
    __shared__ __align__(16) u64 s_w[27 * 16];

    const int tid  = threadIdx.x;
    const int bx   = blockIdx.x;        // 16 tiles of 128 cols
    const int by   = blockIdx.y;        // 512 tiles of 4 rows
    const int row0 = by * 4 - 1;
    const int col0 = bx * 128 - 1;

    // ---- Stage weights (432 values) ----
    if (tid < 432) {
        int oc = tid / 27;
        int t  = tid - oc * 27;
        unsigned u = __float_as_uint(kern[tid]);
        s_w[t * 16 + oc] = ((u64)u << 32) | u;
    }

    // ---- Stage input tile with zero padding (3 * 6 * 130 = 2340 elems) ----
    for (int i = tid; i < 2340; i += 512) {
        int ic  = i / 780;
        int rem = i - ic * 780;
        int r   = rem / 130;
        int c   = rem - r * 130;
        int gy = row0 + r;
        int gx = col0 + c;
        float v = 0.0f;
        if ((unsigned)gy < (unsigned)HW && (unsigned)gx < (unsigned)HW)
            v = x[ic * PLANE + gy * HW + gx];
        s_in[ic][r][c] = v;
    }
    __syncthreads();

    const int tx = tid & 31;            // 32 threads across W (4 px each)
    const int ty = (tid >> 5) & 3;      // 4 rows
    const int og = tid >> 7;            // 4 oc-groups of 4 OC (uniform per warp)

    // acc[oc*2 + p]: oc = local channel (0..3), p = pixel pair (0..1)
    u64 acc[8];
    #pragma unroll
    for (int i = 0; i < 8; ++i) acc[i] = 0ull;

    #pragma unroll
    for (int ic = 0; ic < 3; ++ic) {
        #pragma unroll
        for (int kh = 0; kh < 3; ++kh) {
            const float* rp = &s_in[ic][ty + kh][tx * 4];
            float4 a = *reinterpret_cast<const float4*>(rp);      // v0..v3
            float2 h = *reinterpret_cast<const float2*>(rp + 4);  // v4,v5

            const int t0 = (ic * 9 + kh * 3) * 16 + og * 4;

            // kw = 0: pairs (v0,v1), (v2,v3) — aligned, packs are free-ish
            u64 p01 = pack2(a.x, a.y);
            u64 p23 = pack2(a.z, a.w);
            {
                ulonglong2 wa = *reinterpret_cast<const ulonglong2*>(&s_w[t0]);
                ffma2(acc[0], p01, wa.x); ffma2(acc[1], p23, wa.x);
                ffma2(acc[2], p01, wa.y); ffma2(acc[3], p23, wa.y);
                ulonglong2 wb = *reinterpret_cast<const ulonglong2*>(&s_w[t0 + 2]);
                ffma2(acc[4], p01, wb.x); ffma2(acc[5], p23, wb.x);
                ffma2(acc[6], p01, wb.y); ffma2(acc[7], p23, wb.y);
            }
            // kw = 1: pairs (v1,v2), (v3,v4)
            u64 p12 = pack2(a.y, a.z);
            u64 p34 = pack2(a.w, h.x);
            {
                ulonglong2 wa = *reinterpret_cast<const ulonglong2*>(&s_w[t0 + 16]);
                ffma2(acc[0], p12, wa.x); ffma2(acc[1], p34, wa.x);
                ffma2(acc[2], p12, wa.y); ffma2(acc[3], p34, wa.y);
                ulonglong2 wb = *reinterpret_cast<const ulonglong2*>(&s_w[t0 + 18]);
                ffma2(acc[4], p12, wb.x); ffma2(acc[5], p34, wb.x);
                ffma2(acc[6], p12, wb.y); ffma2(acc[7], p34, wb.y);
            }
            // kw = 2: pairs (v2,v3) reused, (v4,v5)
            u64 p45 = pack2(h.x, h.y);
            {
                ulonglong2 wa = *reinterpret_cast<const ulonglong2*>(&s_w[t0 + 32]);
                ffma2(acc[0], p23, wa.x); ffma2(acc[1], p45, wa.x);
                ffma2(acc[2], p23, wa.y); ffma2(acc[3], p45, wa.y);
                ulonglong2 wb = *reinterpret_cast<const ulonglong2*>(&s_w[t0 + 34]);
                ffma2(acc[4], p23, wb.x); ffma2(acc[5], p45, wb.x);
                ffma2(acc[6], p23, wb.y); ffma2(acc[7], p45, wb.y);
            }
        }
    }

    // ---- Epilogue: 4 oc x float4 coalesced stores ----
    const int orow = by * 4 + ty;
    const int ocol = bx * 128 + tx * 4;
    float* ob = out + (og * 4) * PLANE + orow * HW + ocol;
    #pragma unroll
    for (int oc = 0; oc < 4; ++oc) {
        float2 lo = unpack2(acc[oc * 2 + 0]);
        float2 hi = unpack2(acc[oc * 2 + 1]);
        *reinterpret_cast<float4*>(ob + oc * PLANE) =
            make_float4(lo.x, lo.y, hi.x, hi.y);
    }
}

extern "C" void kernel_launch(void* const* d_in, const int* in_sizes, int n_in,
                              void* d_out, int out_size) {
    const float* x = (const float*)d_in[0];   // [3, 2048, 2048]
    const float* k = (const float*)d_in[1];   // [16, 3, 3, 3]
    float* out     = (float*)d_out;           // [16, 2048, 2048]

    dim3 grid(HW / 128, HW / 4);              // (16, 512)
    conv3x3_f32x2_v6_kernel<<<grid, 512>>>(x, k, out);
}

// round 10
// speedup vs baseline: 1.0017x; 1.0017x over previous
#include <cuda_runtime.h>
#include <cstdint>

// Conv2d: x[3,2048,2048] fp32 * k[16,3,3,3] fp32, pad=1, stride=1 -> out[16,2048,2048]
//
// R8: direct conv, fma.rn.f32x2, crossbar-byte-minimal loads + high occupancy.
//   - block = 512 threads: 32 tx (4 px) x 4 ty (rows) x 4 og (4 OC each).
//     Tile = 4 rows x 128 cols x 16 OC. grid (16, 512).
//   - input rows plain fp32 in smem; per tap-row ONE float4 + ONE float2
//     (24 B/thread, each value loaded once); shifted pairs built with packs.
//   - weights (w,w)-packed u64, warp-uniform ulonglong2 loads, sequenced wa->wb.
//   - __launch_bounds__(512,3): 42-reg cap, 3 CTAs x 16 warps = 48 warps/SM (75% occ).
//   - per thread: 216 FFMA2, 18 input LDS, 54 weight LDS, ~45 pack MOVs.

#define HW    2048
#define PLANE (2048 * 2048)

typedef unsigned long long u64;

__device__ __forceinline__ u64 pack2(float a, float b) {
    u64 r;
    asm("mov.b64 %0, {%1, %2};"
        : "=l"(r) : "r"(__float_as_uint(a)), "r"(__float_as_uint(b)));
    return r;
}

__device__ __forceinline__ void ffma2(u64& d, u64 a, u64 b) {
    asm("fma.rn.f32x2 %0, %1, %2, %0;" : "+l"(d) : "l"(a), "l"(b));
}

__device__ __forceinline__ float2 unpack2(u64 v) {
    unsigned lo, hi;
    asm("mov.b64 {%0, %1}, %2;" : "=r"(lo), "=r"(hi) : "l"(v));
    return make_float2(__uint_as_float(lo), __uint_as_float(hi));
}

__global__ __launch_bounds__(512, 3)
void conv3x3_f32x2_v6_kernel(const float* __restrict__ x,
                             const float* __restrict__ kern,
                             float* __restrict__ out) {
    // Input tile: 3 ch, 4+2 rows, 128+2 cols padded to 132 (16B-aligned rows).
    __shared__ __align__(16) float s_in[3][6][132];
    // Weights (w,w)-packed, layout [tap][oc16], tap = ic*9 + kh*3 + kw.
    __shared__ __align__(16) u64 s_w[27 * 16];

    const int tid  = threadIdx.x;
    const int bx   = blockIdx.x;        // 16 tiles of 128 cols
    const int by   = blockIdx.y;        // 512 tiles of 4 rows
    const int row0 = by * 4 - 1;
    const int col0 = bx * 128 - 1;

    // ---- Stage weights (432 values) ----
    if (tid < 432) {
        int oc = tid / 27;
        int t  = tid - oc * 27;
        unsigned u = __float_as_uint(kern[tid]);
        s_w[t * 16 + oc] = ((u64)u << 32) | u;
    }

    // ---- Stage input tile with zero padding (3 * 6 * 130 = 2340 elems) ----
    for (int i = tid; i < 2340; i += 512) {
        int ic  = i / 780;
        int rem = i - ic * 780;
        int r   = rem / 130;
        int c   = rem - r * 130;
        int gy = row0 + r;
        int gx = col0 + c;
        float v = 0.0f;
        if ((unsigned)gy < (unsigned)HW && (unsigned)gx < (unsigned)HW)
            v = x[ic * PLANE + gy * HW + gx];
        s_in[ic][r][c] = v;
    }
    __syncthreads();

    const int tx = tid & 31;            // 32 threads across W (4 px each)
    const int ty = (tid >> 5) & 3;      // 4 rows
    const int og = tid >> 7;            // 4 oc-groups of 4 OC (uniform per warp)

    // acc[oc*2 + p]: oc = local channel (0..3), p = pixel pair (0..1)
    u64 acc[8];
    #pragma unroll
    for (int i = 0; i < 8; ++i) acc[i] = 0ull;

    #pragma unroll
    for (int ic = 0; ic < 3; ++ic) {
        #pragma unroll
        for (int kh = 0; kh < 3; ++kh) {
            const float* rp = &s_in[ic][ty + kh][tx * 4];
            float4 a = *reinterpret_cast<const float4*>(rp);      // v0..v3
            float2 h = *reinterpret_cast<const float2*>(rp + 4);  // v4,v5

            const int t0 = (ic * 9 + kh * 3) * 16 + og * 4;

            // kw = 0: pairs (v0,v1), (v2,v3) — aligned, packs are free-ish
            u64 p01 = pack2(a.x, a.y);
            u64 p23 = pack2(a.z, a.w);
            {
                ulonglong2 wa = *reinterpret_cast<const ulonglong2*>(&s_w[t0]);
                ffma2(acc[0], p01, wa.x); ffma2(acc[1], p23, wa.x);
                ffma2(acc[2], p01, wa.y); ffma2(acc[3], p23, wa.y);
                ulonglong2 wb = *reinterpret_cast<const ulonglong2*>(&s_w[t0 + 2]);
                ffma2(acc[4], p01, wb.x); ffma2(acc[5], p23, wb.x);
                ffma2(acc[6], p01, wb.y); ffma2(acc[7], p23, wb.y);
            }
            // kw = 1: pairs (v1,v2), (v3,v4)
            u64 p12 = pack2(a.y, a.z);
            u64 p34 = pack2(a.w, h.x);
            {
                ulonglong2 wa = *reinterpret_cast<const ulonglong2*>(&s_w[t0 + 16]);
                ffma2(acc[0], p12, wa.x); ffma2(acc[1], p34, wa.x);
                ffma2(acc[2], p12, wa.y); ffma2(acc[3], p34, wa.y);
                ulonglong2 wb = *reinterpret_cast<const ulonglong2*>(&s_w[t0 + 18]);
                ffma2(acc[4], p12, wb.x); ffma2(acc[5], p34, wb.x);
                ffma2(acc[6], p12, wb.y); ffma2(acc[7], p34, wb.y);
            }
            // kw = 2: pairs (v2,v3) reused, (v4,v5)
            u64 p45 = pack2(h.x, h.y);
            {
                ulonglong2 wa = *reinterpret_cast<const ulonglong2*>(&s_w[t0 + 32]);
                ffma2(acc[0], p23, wa.x); ffma2(acc[1], p45, wa.x);
                ffma2(acc[2], p23, wa.y); ffma2(acc[3], p45, wa.y);
                ulonglong2 wb = *reinterpret_cast<const ulonglong2*>(&s_w[t0 + 34]);
                ffma2(acc[4], p23, wb.x); ffma2(acc[5], p45, wb.x);
                ffma2(acc[6], p23, wb.y); ffma2(acc[7], p45, wb.y);
            }
        }
    }

    // ---- Epilogue: 4 oc x float4 coalesced stores ----
    const int orow = by * 4 + ty;
    const int ocol = bx * 128 + tx * 4;
    float* ob = out + (og * 4) * PLANE + orow * HW + ocol;
    #pragma unroll
    for (int oc = 0; oc < 4; ++oc) {
        float2 lo = unpack2(acc[oc * 2 + 0]);
        float2 hi = unpack2(acc[oc * 2 + 1]);
        *reinterpret_cast<float4*>(ob + oc * PLANE) =
            make_float4(lo.x, lo.y, hi.x, hi.y);
    }
}

extern "C" void kernel_launch(void* const* d_in, const int* in_sizes, int n_in,
                              void* d_out, int out_size) {
    const float* x = (const float*)d_in[0];   // [3, 2048, 2048]
    const float* k = (const float*)d_in[1];   // [16, 3, 3, 3]
    float* out     = (float*)d_out;           // [16, 2048, 2048]

    dim3 grid(HW / 128, HW / 4);              // (16, 512)
    conv3x3_f32x2_v6_kernel<<<grid, 512>>>(x, k, out);
}

// round 11
// speedup vs baseline: 1.0020x; 1.0002x over previous
#include <cuda_runtime.h>
#include <cstdint>

// Conv2d: x[3,2048,2048] fp32 * k[16,3,3,3] fp32, pad=1, stride=1 -> out[16,2048,2048]
//
// R8: direct conv, fma.rn.f32x2, crossbar-byte-minimal loads + high occupancy.
//   - block = 512 threads: 32 tx (4 px) x 4 ty (rows) x 4 og (4 OC each).
//     Tile = 4 rows x 128 cols x 16 OC. grid (16, 512).
//   - input rows plain fp32 in smem; per tap-row ONE float4 + ONE float2
//     (24 B/thread, each value loaded once); shifted pairs built with packs.
//   - weights (w,w)-packed u64, warp-uniform ulonglong2 loads, sequenced wa->wb.
//   - __launch_bounds__(512,3): 42-reg cap, 3 CTAs x 16 warps = 48 warps/SM (75% occ).
//   - per thread: 216 FFMA2, 18 input LDS, 54 weight LDS, ~45 pack MOVs.

#define HW    2048
#define PLANE (2048 * 2048)

typedef unsigned long long u64;

__device__ __forceinline__ u64 pack2(float a, float b) {
    u64 r;
    asm("mov.b64 %0, {%1, %2};"
        : "=l"(r) : "r"(__float_as_uint(a)), "r"(__float_as_uint(b)));
    return r;
}

__device__ __forceinline__ void ffma2(u64& d, u64 a, u64 b) {
    asm("fma.rn.f32x2 %0, %1, %2, %0;" : "+l"(d) : "l"(a), "l"(b));
}

__device__ __forceinline__ float2 unpack2(u64 v) {
    unsigned lo, hi;
    asm("mov.b64 {%0, %1}, %2;" : "=r"(lo), "=r"(hi) : "l"(v));
    return make_float2(__uint_as_float(lo), __uint_as_float(hi));
}

__global__ __launch_bounds__(512, 3)
void conv3x3_f32x2_v6_kernel(const float* __restrict__ x,
                             const float* __restrict__ kern,
                             float* __restrict__ out) {
    // Input tile: 3 ch, 4+2 rows, 128+2 cols padded to 132 (16B-aligned rows).
    __shared__ __align__(16) float s_in[3][6][132];
    // Weights (w,w)-packed, layout [tap][oc16], tap = ic*9 + kh*3 + kw.
    __shared__ __align__(16) u64 s_w[27 * 16];

    const int tid  = threadIdx.x;
    const int bx   = blockIdx.x;        // 16 tiles of 128 cols
    const int by   = blockIdx.y;        // 512 tiles of 4 rows
    const int row0 = by * 4 - 1;
    const int col0 = bx * 128 - 1;

    // ---- Stage weights (432 values) ----
    if (tid < 432) {
        int oc = tid / 27;
        int t  = tid - oc * 27;
        unsigned u = __float_as_uint(kern[tid]);
        s_w[t * 16 + oc] = ((u64)u << 32) | u;
    }

    // ---- Stage input tile with zero padding (3 * 6 * 130 = 2340 elems) ----
    for (int i = tid; i < 2340; i += 512) {
        int ic  = i / 780;
        int rem = i - ic * 780;
        int r   = rem / 130;
        int c   = rem - r * 130;
        int gy = row0 + r;
        int gx = col0 + c;
        float v = 0.0f;
        if ((unsigned)gy < (unsigned)HW && (unsigned)gx < (unsigned)HW)
            v = x[ic * PLANE + gy * HW + gx];
        s_in[ic][r][c] = v;
    }
    __syncthreads();

    const int tx = tid & 31;            // 32 threads across W (4 px each)
    const int ty = (tid >> 5) & 3;      // 4 rows
    const int og = tid >> 7;            // 4 oc-groups of 4 OC (uniform per warp)

    // acc[oc*2 + p]: oc = local channel (0..3), p = pixel pair (0..1)
    u64 acc[8];
    #pragma unroll
    for (int i = 0; i < 8; ++i) acc[i] = 0ull;

    #pragma unroll
    for (int ic = 0; ic < 3; ++ic) {
        #pragma unroll
        for (int kh = 0; kh < 3; ++kh) {
            const float* rp = &s_in[ic][ty + kh][tx * 4];
            float4 a = *reinterpret_cast<const float4*>(rp);      // v0..v3
            float2 h = *reinterpret_cast<const float2*>(rp + 4);  // v4,v5

            const int t0 = (ic * 9 + kh * 3) * 16 + og * 4;

            // kw = 0: pairs (v0,v1), (v2,v3) — aligned, packs are free-ish
            u64 p01 = pack2(a.x, a.y);
            u64 p23 = pack2(a.z, a.w);
            {
                ulonglong2 wa = *reinterpret_cast<const ulonglong2*>(&s_w[t0]);
                ffma2(acc[0], p01, wa.x); ffma2(acc[1], p23, wa.x);
                ffma2(acc[2], p01, wa.y); ffma2(acc[3], p23, wa.y);
                ulonglong2 wb = *reinterpret_cast<const ulonglong2*>(&s_w[t0 + 2]);
                ffma2(acc[4], p01, wb.x); ffma2(acc[5], p23, wb.x);
                ffma2(acc[6], p01, wb.y); ffma2(acc[7], p23, wb.y);
            }
            // kw = 1: pairs (v1,v2), (v3,v4)
            u64 p12 = pack2(a.y, a.z);
            u64 p34 = pack2(a.w, h.x);
            {
                ulonglong2 wa = *reinterpret_cast<const ulonglong2*>(&s_w[t0 + 16]);
                ffma2(acc[0], p12, wa.x); ffma2(acc[1], p34, wa.x);
                ffma2(acc[2], p12, wa.y); ffma2(acc[3], p34, wa.y);
                ulonglong2 wb = *reinterpret_cast<const ulonglong2*>(&s_w[t0 + 18]);
                ffma2(acc[4], p12, wb.x); ffma2(acc[5], p34, wb.x);
                ffma2(acc[6], p12, wb.y); ffma2(acc[7], p34, wb.y);
            }
            // kw = 2: pairs (v2,v3) reused, (v4,v5)
            u64 p45 = pack2(h.x, h.y);
            {
                ulonglong2 wa = *reinterpret_cast<const ulonglong2*>(&s_w[t0 + 32]);
                ffma2(acc[0], p23, wa.x); ffma2(acc[1], p45, wa.x);
                ffma2(acc[2], p23, wa.y); ffma2(acc[3], p45, wa.y);
                ulonglong2 wb = *reinterpret_cast<const ulonglong2*>(&s_w[t0 + 34]);
                ffma2(acc[4], p23, wb.x); ffma2(acc[5], p45, wb.x);
                ffma2(acc[6], p23, wb.y); ffma2(acc[7], p45, wb.y);
            }
        }
    }

    // ---- Epilogue: 4 oc x float4 coalesced stores ----
    const int orow = by * 4 + ty;
    const int ocol = bx * 128 + tx * 4;
    float* ob = out + (og * 4) * PLANE + orow * HW + ocol;
    #pragma unroll
    for (int oc = 0; oc < 4; ++oc) {
        float2 lo = unpack2(acc[oc * 2 + 0]);
        float2 hi = unpack2(acc[oc * 2 + 1]);
        *reinterpret_cast<float4*>(ob + oc * PLANE) =
            make_float4(lo.x, lo.y, hi.x, hi.y);
    }
}

extern "C" void kernel_launch(void* const* d_in, const int* in_sizes, int n_in,
                              void* d_out, int out_size) {
    const float* x = (const float*)d_in[0];   // [3, 2048, 2048]
    const float* k = (const float*)d_in[1];   // [16, 3, 3, 3]
    float* out     = (float*)d_out;           // [16, 2048, 2048]

    dim3 grid(HW / 128, HW / 4);              // (16, 512)
    conv3x3_f32x2_v6_kernel<<<grid, 512>>>(x, k, out);
}

// round 12
// speedup vs baseline: 1.0352x; 1.0331x over previous
#include <cuda_runtime.h>
#include <cstdint>

// Conv2d: x[3,2048,2048] fp32 * k[16,3,3,3] fp32, pad=1, stride=1 -> out[16,2048,2048]
//
// R11 (v7): R7's zero-pack pre-paired loop + software-pipelined tap-row loads.
//   - block = 512 threads: 32 tx (4 px) x 4 ty (rows) x 4 og (4 OC each).
//     Tile = 4 rows x 128 cols x 16 OC. grid (16, 512).
//   - __launch_bounds__(512,3): 42-reg cap -> 48 warps/SM (75% occ).
//   - input tile pre-paired in smem (slot c = (v[c],v[c+1]) at [c&3][c>>2]):
//     every shifted pair is one conflict-free LDS.64, zero pack MOVs.
//   - DOUBLE-BUFFERED prefetch: tap-row t+1's 5 pairs are loaded before tap-row
//     t's 24 FFMA2 (>= 48 cyc of independent work vs LDS lat 29) -> stalls hidden.
//   - weights (w,w)-packed u64, warp-uniform broadcast ulonglong2, sequenced.

#define HW    2048
#define PLANE (2048 * 2048)

typedef unsigned long long u64;

__device__ __forceinline__ void ffma2(u64& d, u64 a, u64 b) {
    asm("fma.rn.f32x2 %0, %1, %2, %0;" : "+l"(d) : "l"(a), "l"(b));
}

__device__ __forceinline__ float2 unpack2(u64 v) {
    unsigned lo, hi;
    asm("mov.b64 {%0, %1}, %2;" : "=r"(lo), "=r"(hi) : "l"(v));
    return make_float2(__uint_as_float(lo), __uint_as_float(hi));
}

__device__ __forceinline__ u64 lds_pair(const float2* p) {
    return *reinterpret_cast<const u64*>(p);
}

// Load the 5 shifted pairs of one tap-row: p01,p12,p23,p34,p45.
__device__ __forceinline__ void load_row(u64* b, const float2 (*row)[34], int tx) {
    b[0] = lds_pair(&row[0][tx]);        // p01
    b[1] = lds_pair(&row[1][tx]);        // p12
    b[2] = lds_pair(&row[2][tx]);        // p23
    b[3] = lds_pair(&row[3][tx]);        // p34
    b[4] = lds_pair(&row[0][tx + 1]);    // p45
}

__global__ __launch_bounds__(512, 3)
void conv3x3_f32x2_v7_kernel(const float* __restrict__ x,
                             const float* __restrict__ kern,
                             float* __restrict__ out) {
    // Pair tile: slot s (0..128) holds (v[s], v[s+1]) at [s&3][s>>2]. 6 rows (4+halo).
    __shared__ float2 s_pair[3][6][4][34];
    // Weights (w,w)-packed, layout [tap][oc16], tap = ic*9 + kh*3 + kw.
    __shared__ __align__(16) u64 s_w[27 * 16];

    const int tid  = threadIdx.x;
    const int bx   = blockIdx.x;        // 16 tiles of 128 cols
    const int by   = blockIdx.y;        // 512 tiles of 4 rows
    const int row0 = by * 4 - 1;
    const int col0 = bx * 128 - 1;

    // ---- Stage weights (432 values) ----
    if (tid < 432) {
        int oc = tid / 27;
        int t  = tid - oc * 27;
        unsigned u = __float_as_uint(kern[tid]);
        s_w[t * 16 + oc] = ((u64)u << 32) | u;
    }

    // ---- Stage input tile as adjacent pairs, zero-padded (3 * 6 * 130 values) ----
    for (int i = tid; i < 2340; i += 512) {
        int ic  = i / 780;
        int rem = i - ic * 780;
        int r   = rem / 130;
        int c   = rem - r * 130;        // 0..129
        int gy = row0 + r;
        int gx = col0 + c;
        float v = 0.0f;
        if ((unsigned)gy < (unsigned)HW && (unsigned)gx < (unsigned)HW)
            v = x[ic * PLANE + gy * HW + gx];
        s_pair[ic][r][c & 3][c >> 2].x = v;
        if (c > 0)
            s_pair[ic][r][(c - 1) & 3][(c - 1) >> 2].y = v;
    }
    __syncthreads();

    const int tx = tid & 31;            // 32 threads across W (4 px each)
    const int ty = (tid >> 5) & 3;      // 4 rows
    const int og = tid >> 7;            // 4 oc-groups of 4 OC (uniform per warp)

    // acc[2*oc + p]: oc = local channel (0..3), p = pixel pair (0..1)
    u64 acc[8];
    #pragma unroll
    for (int i = 0; i < 8; ++i) acc[i] = 0ull;

    // Double-buffered tap-row pipeline over t = ic*3 + kh (9 tap-rows).
    u64 buf[2][5];
    load_row(buf[0], s_pair[0][ty], tx);

    #pragma unroll
    for (int t = 0; t < 9; ++t) {
        // Prefetch next tap-row's pairs into the other buffer.
        if (t < 8) {
            const int t1  = t + 1;
            const int ic1 = t1 / 3;
            const int kh1 = t1 - ic1 * 3;
            load_row(buf[(t + 1) & 1], s_pair[ic1][ty + kh1], tx);
        }
        const u64* b = buf[t & 1];
        const int  w0 = 48 * t + og * 4;     // tap base = (3t)*16

        {   // kw = 0: pairs (p01, p23)
            ulonglong2 wa = *reinterpret_cast<const ulonglong2*>(&s_w[w0]);
            ffma2(acc[0], b[0], wa.x); ffma2(acc[1], b[2], wa.x);
            ffma2(acc[2], b[0], wa.y); ffma2(acc[3], b[2], wa.y);
            ulonglong2 wb = *reinterpret_cast<const ulonglong2*>(&s_w[w0 + 2]);
            ffma2(acc[4], b[0], wb.x); ffma2(acc[5], b[2], wb.x);
            ffma2(acc[6], b[0], wb.y); ffma2(acc[7], b[2], wb.y);
        }
        {   // kw = 1: pairs (p12, p34)
            ulonglong2 wa = *reinterpret_cast<const ulonglong2*>(&s_w[w0 + 16]);
            ffma2(acc[0], b[1], wa.x); ffma2(acc[1], b[3], wa.x);
            ffma2(acc[2], b[1], wa.y); ffma2(acc[3], b[3], wa.y);
            ulonglong2 wb = *reinterpret_cast<const ulonglong2*>(&s_w[w0 + 18]);
            ffma2(acc[4], b[1], wb.x); ffma2(acc[5], b[3], wb.x);
            ffma2(acc[6], b[1], wb.y); ffma2(acc[7], b[3], wb.y);
        }
        {   // kw = 2: pairs (p23, p45)
            ulonglong2 wa = *reinterpret_cast<const ulonglong2*>(&s_w[w0 + 32]);
            ffma2(acc[0], b[2], wa.x); ffma2(acc[1], b[4], wa.x);
            ffma2(acc[2], b[2], wa.y); ffma2(acc[3], b[4], wa.y);
            ulonglong2 wb = *reinterpret_cast<const ulonglong2*>(&s_w[w0 + 34]);
            ffma2(acc[4], b[2], wb.x); ffma2(acc[5], b[4], wb.x);
            ffma2(acc[6], b[2], wb.y); ffma2(acc[7], b[4], wb.y);
        }
    }

    // ---- Epilogue: 4 oc x float4 coalesced stores ----
    const int orow = by * 4 + ty;
    const int ocol = bx * 128 + tx * 4;
    float* ob = out + (og * 4) * PLANE + orow * HW + ocol;
    #pragma unroll
    for (int oc = 0; oc < 4; ++oc) {
        float2 lo = unpack2(acc[oc * 2 + 0]);
        float2 hi = unpack2(acc[oc * 2 + 1]);
        *reinterpret_cast<float4*>(ob + oc * PLANE) =
            make_float4(lo.x, lo.y, hi.x, hi.y);
    }
}

extern "C" void kernel_launch(void* const* d_in, const int* in_sizes, int n_in,
                              void* d_out, int out_size) {
    const float* x = (const float*)d_in[0];   // [3, 2048, 2048]
    const float* k = (const float*)d_in[1];   // [16, 3, 3, 3]
    float* out     = (float*)d_out;           // [16, 2048, 2048]

    dim3 grid(HW / 128, HW / 4);              // (16, 512)
    conv3x3_f32x2_v7_kernel<<<grid, 512>>>(x, k, out);
}